// round 2
// baseline (speedup 1.0000x reference)
#include <cuda_runtime.h>
#include <cstdint>

// Problem constants
#define TT 64
#define BB 256
#define N_IN 1024
#define N_H 4096
#define N_OUT 1024

__device__ __constant__ float c_alpha = 0.05f;   // DT/TAU
__device__ __constant__ float c_thr   = 1.0f;

// ---------------- persistent device state (no allocs allowed) ----------------
__device__ float g_v_in [BB * N_IN];
__device__ float g_v_h  [BB * N_H];
__device__ float g_v_out[BB * N_OUT];

// Spike index lists, triple-buffered.
// Step t: reads buf (t%3), writes buf ((t+1)%3), zeros counts of buf ((t+2)%3).
__device__ int g_cnt_in[3][BB];
__device__ int g_cnt_h [3][BB];
__device__ int g_list_in[3][BB][N_IN];   // worst-case capacity: every neuron spikes
__device__ int g_list_h [3][BB][N_H];

// ---------------- init: reset all state (graph is replayed many times) -------
__global__ void snn_init_kernel() {
    int i = blockIdx.x * blockDim.x + threadIdx.x;
    int stride = gridDim.x * blockDim.x;
    for (int k = i; k < BB * N_H;   k += stride) g_v_h[k]   = 0.f;
    for (int k = i; k < BB * N_IN;  k += stride) g_v_in[k]  = 0.f;
    for (int k = i; k < BB * N_OUT; k += stride) g_v_out[k] = 0.f;
    if (i < BB) {
        #pragma unroll
        for (int buf = 0; buf < 3; buf++) {
            g_cnt_in[buf][i] = 0;
            g_cnt_h [buf][i] = 0;
        }
    }
}

// ---------------- one fused timestep --------------------------------------
// Thread layout (each thread processes 4 contiguous neurons, float4):
//   [0, BB*N_H/4)                    : hidden population
//   [BB*N_H/4, +BB*N_IN/4)           : input population
//   [.., +BB*N_OUT/4)                : output population
__global__ void snn_step_kernel(const float* __restrict__ x_ext,
                                const float* __restrict__ W_ih,
                                const float* __restrict__ W_hh,
                                const float* __restrict__ W_ho,
                                float* __restrict__ out,
                                int t) {
    const int rd = t % 3;
    const int wr = (t + 1) % 3;
    const int zr = (t + 2) % 3;
    const float alpha = c_alpha;
    const float thr   = c_thr;

    int gid = blockIdx.x * blockDim.x + threadIdx.x;

    const int HID_T = (BB * N_H) / 4;     // 262144
    const int IN_T  = (BB * N_IN) / 4;    // 65536

    // fold count-zeroing of buffer zr into the first BB threads
    if (gid < BB) {
        g_cnt_in[zr][gid] = 0;
        g_cnt_h [zr][gid] = 0;
    }

    if (gid < HID_T) {
        int e  = gid * 4;
        int b  = e / N_H;
        int j0 = e % N_H;

        float4 v4 = *reinterpret_cast<const float4*>(g_v_h + e);
        float vv[4] = {v4.x, v4.y, v4.z, v4.w};
        float I [4] = {0.f, 0.f, 0.f, 0.f};

        // synaptic input: sparse gather from previous-step spike lists
        const int cin = g_cnt_in[rd][b];
        for (int k = 0; k < cin; k++) {
            const int i = g_list_in[rd][b][k];
            const float* wrow = W_ih + i;               // column i of W_ih.T
            #pragma unroll
            for (int l = 0; l < 4; l++) I[l] += wrow[(size_t)(j0 + l) * N_IN];
        }
        const int ch = g_cnt_h[rd][b];
        for (int k = 0; k < ch; k++) {
            const int i = g_list_h[rd][b][k];
            const float* wrow = W_hh + i;
            #pragma unroll
            for (int l = 0; l < 4; l++) I[l] += wrow[(size_t)(j0 + l) * N_H];
        }

        #pragma unroll
        for (int l = 0; l < 4; l++) {
            float v = vv[l] + alpha * (I[l] - vv[l]);
            if (v >= thr) {
                int p = atomicAdd(&g_cnt_h[wr][b], 1);
                g_list_h[wr][b][p] = j0 + l;
                v = 0.f;
            }
            vv[l] = v;
        }
        *reinterpret_cast<float4*>(g_v_h + e) =
            make_float4(vv[0], vv[1], vv[2], vv[3]);

    } else if (gid < HID_T + IN_T) {
        int e  = (gid - HID_T) * 4;
        int b  = e / N_IN;
        int i0 = e % N_IN;

        float4 x4 = *reinterpret_cast<const float4*>(
            x_ext + (size_t)t * BB * N_IN + e);
        float4 v4 = *reinterpret_cast<const float4*>(g_v_in + e);
        float xx[4] = {x4.x, x4.y, x4.z, x4.w};
        float vv[4] = {v4.x, v4.y, v4.z, v4.w};

        #pragma unroll
        for (int l = 0; l < 4; l++) {
            float v = vv[l] + alpha * (xx[l] - vv[l]);
            if (v >= thr) {
                int p = atomicAdd(&g_cnt_in[wr][b], 1);
                g_list_in[wr][b][p] = i0 + l;
                v = 0.f;
            }
            vv[l] = v;
        }
        *reinterpret_cast<float4*>(g_v_in + e) =
            make_float4(vv[0], vv[1], vv[2], vv[3]);

    } else {
        int e  = (gid - HID_T - IN_T) * 4;
        int b  = e / N_OUT;
        int o0 = e % N_OUT;

        float4 v4 = *reinterpret_cast<const float4*>(g_v_out + e);
        float vv[4] = {v4.x, v4.y, v4.z, v4.w};
        float I [4] = {0.f, 0.f, 0.f, 0.f};

        const int ch = g_cnt_h[rd][b];
        for (int k = 0; k < ch; k++) {
            const int i = g_list_h[rd][b][k];
            const float* wrow = W_ho + i;
            #pragma unroll
            for (int l = 0; l < 4; l++) I[l] += wrow[(size_t)(o0 + l) * N_H];
        }

        float ss[4];
        #pragma unroll
        for (int l = 0; l < 4; l++) {
            float v = vv[l] + alpha * (I[l] - vv[l]);
            float s = (v >= thr) ? 1.0f : 0.0f;
            ss[l] = s;
            vv[l] = v * (1.0f - s);
        }
        *reinterpret_cast<float4*>(g_v_out + e) =
            make_float4(vv[0], vv[1], vv[2], vv[3]);
        *reinterpret_cast<float4*>(out + (size_t)t * BB * N_OUT + e) =
            make_float4(ss[0], ss[1], ss[2], ss[3]);
    }
}

// ---------------- launch ----------------------------------------------------
extern "C" void kernel_launch(void* const* d_in, const int* in_sizes, int n_in,
                              void* d_out, int out_size) {
    const float* x_ext = (const float*)d_in[0];  // [T, B, N_IN]
    const float* W_ih  = (const float*)d_in[1];  // [N_H, N_IN]
    const float* W_hh  = (const float*)d_in[2];  // [N_H, N_H]
    const float* W_ho  = (const float*)d_in[3];  // [N_OUT, N_H]
    float* out = (float*)d_out;                  // [T, B, N_OUT]

    snn_init_kernel<<<256, 256>>>();

    const int total_threads = (BB * (N_H + N_IN + N_OUT)) / 4;  // 393216
    const int block = 256;
    const int grid  = total_threads / block;                    // 1536

    for (int t = 0; t < TT; t++) {
        snn_step_kernel<<<grid, block>>>(x_ext, W_ih, W_hh, W_ho, out, t);
    }
}

// round 3
// speedup vs baseline: 7.1700x; 7.1700x over previous
#include <cuda_runtime.h>
#include <cstdint>

#define TT 64
#define BB 256
#define N_IN 1024
#define N_H 4096
#define N_OUT 1024

#define ALPHA 0.05f
#define THR   1.0f

// ---------------- persistent device state (statics; no runtime allocs) ------
__device__ float g_v_h  [BB * N_H];     // 4 MB   (slow path only)
__device__ float g_v_out[BB * N_OUT];   // 1 MB   (slow path only)

// input spike lists for every step (worst case full), hidden double-buffered
__device__ int g_in_cnt [TT][BB];
__device__ int g_in_list[TT][BB][N_IN];     // 64 MB worst case
__device__ int g_h_cnt  [TT][BB];
__device__ int g_h_list [2][BB][N_H];       // 8 MB
__device__ int g_total_in;

// custom grid barrier state (monotonic epoch; arrive resets itself)
__device__ unsigned int          g_bar_arrive;
__device__ volatile unsigned int g_bar_epoch;

// ---------------- init: reset counters + slow-path state --------------------
__global__ void snn_init_kernel() {
    int gid = blockIdx.x * blockDim.x + threadIdx.x;
    int stride = gridDim.x * blockDim.x;
    for (int k = gid; k < TT * BB; k += stride) {
        ((int*)g_in_cnt)[k] = 0;
        ((int*)g_h_cnt)[k]  = 0;
    }
    for (int k = gid; k < BB * N_H;   k += stride) g_v_h[k]   = 0.f;
    for (int k = gid; k < BB * N_OUT; k += stride) g_v_out[k] = 0.f;
    if (gid == 0) {
        g_total_in   = 0;
        g_bar_arrive = 0;
        // g_bar_epoch stays monotonic across replays (barrier is epoch-relative)
    }
}

// ---------------- kernel A: full-T input-population scan + zero out ---------
// One thread per (b, i) input neuron; v lives in a register across all T steps.
// Also zeroes the entire output tensor (fast path leaves it as the answer).
__global__ void snn_input_scan_kernel(const float* __restrict__ x_ext,
                                      float* __restrict__ out) {
    int gid = blockIdx.x * blockDim.x + threadIdx.x;   // 0 .. 262143
    int b = gid >> 10;          // / N_IN
    int i = gid & (N_IN - 1);

    const size_t base = (size_t)b * N_IN + i;
    float v = 0.f;
    #pragma unroll 4
    for (int t = 0; t < TT; t++) {
        float xv = x_ext[(size_t)t * (BB * N_IN) + base];
        v += ALPHA * (xv - v);
        if (v >= THR) {
            int p = atomicAdd(&g_in_cnt[t][b], 1);
            g_in_list[t][b][p] = i;
            atomicAdd(&g_total_in, 1);
            v = 0.f;
        }
    }

    // zero the output tensor (valid final answer when network is silent)
    float4* o4 = (float4*)out;
    const int tot4 = TT * BB * N_OUT / 4;              // 4,194,304
    const int nt   = gridDim.x * blockDim.x;           // 262,144
    for (int k = gid; k < tot4; k += nt)
        o4[k] = make_float4(0.f, 0.f, 0.f, 0.f);
}

// ---------------- grid barrier (all blocks guaranteed co-resident) ----------
__device__ __forceinline__ void grid_barrier(unsigned int nblocks) {
    __syncthreads();
    if (threadIdx.x == 0) {
        __threadfence();
        unsigned int e = g_bar_epoch;
        unsigned int a = atomicAdd(&g_bar_arrive, 1u);
        if (a == nblocks - 1u) {
            g_bar_arrive = 0u;
            __threadfence();
            g_bar_epoch = e + 1u;
        } else {
            while (g_bar_epoch == e) { __nanosleep(64); }
        }
        __threadfence();
    }
    __syncthreads();
}

// ---------------- kernel B: hidden/output dynamics --------------------------
// Fast path: zero input spikes anywhere => v_h == v_out == 0 for all t,
// output is all zeros (already written by kernel A) => immediate exit.
// Slow path: exact sequential emulation with one grid barrier per step.
#define DYN_BLOCKS 148
#define DYN_THREADS 1024

__global__ __launch_bounds__(DYN_THREADS, 1)
void snn_dynamics_kernel(const float* __restrict__ W_ih,
                         const float* __restrict__ W_hh,
                         const float* __restrict__ W_ho,
                         float* __restrict__ out) {
    if (g_total_in == 0) return;   // silent network: done.

    const int gtid = blockIdx.x * blockDim.x + threadIdx.x;
    const int NT   = DYN_BLOCKS * DYN_THREADS;         // 151,552

    for (int t = 0; t < TT; t++) {
        // ---- hidden population -----------------------------------------
        for (int idx = gtid; idx < BB * N_H; idx += NT) {
            int b = idx >> 12;            // / N_H
            int j = idx & (N_H - 1);
            float v = g_v_h[idx];
            float I = 0.f;
            if (t > 0) {
                const int ci = g_in_cnt[t - 1][b];
                for (int k = 0; k < ci; k++)
                    I += W_ih[(size_t)j * N_IN + g_in_list[t - 1][b][k]];
                const int ch = g_h_cnt[t - 1][b];
                const int* hl = g_h_list[(t - 1) & 1][b];
                for (int k = 0; k < ch; k++)
                    I += W_hh[(size_t)j * N_H + hl[k]];
            }
            v += ALPHA * (I - v);
            if (v >= THR) {
                int p = atomicAdd(&g_h_cnt[t][b], 1);
                g_h_list[t & 1][b][p] = j;
                v = 0.f;
            }
            g_v_h[idx] = v;
        }
        // ---- output population -----------------------------------------
        for (int idx = gtid; idx < BB * N_OUT; idx += NT) {
            int b = idx >> 10;            // / N_OUT
            int o = idx & (N_OUT - 1);
            float v = g_v_out[idx];
            float I = 0.f;
            if (t > 0) {
                const int ch = g_h_cnt[t - 1][b];
                const int* hl = g_h_list[(t - 1) & 1][b];
                for (int k = 0; k < ch; k++)
                    I += W_ho[(size_t)o * N_H + hl[k]];
            }
            v += ALPHA * (I - v);
            float s = (v >= THR) ? 1.f : 0.f;
            out[(size_t)t * (BB * N_OUT) + idx] = s;
            g_v_out[idx] = v * (1.f - s);
        }
        // spikes of step t must be complete before step t+1 consumes them
        grid_barrier(DYN_BLOCKS);
    }
}

// ---------------- launch ----------------------------------------------------
extern "C" void kernel_launch(void* const* d_in, const int* in_sizes, int n_in,
                              void* d_out, int out_size) {
    const float* x_ext = (const float*)d_in[0];  // [T, B, N_IN]
    const float* W_ih  = (const float*)d_in[1];  // [N_H, N_IN]
    const float* W_hh  = (const float*)d_in[2];  // [N_H, N_H]
    const float* W_ho  = (const float*)d_in[3];  // [N_OUT, N_H]
    float* out = (float*)d_out;                  // [T, B, N_OUT]

    snn_init_kernel<<<1024, 256>>>();
    snn_input_scan_kernel<<<1024, 256>>>(x_ext, out);   // 262,144 threads
    snn_dynamics_kernel<<<DYN_BLOCKS, DYN_THREADS>>>(W_ih, W_hh, W_ho, out);
}